// round 15
// baseline (speedup 1.0000x reference)
#include <cuda_runtime.h>
#include <cuda_fp16.h>
#include <cstdint>

// LSTMPredictor B=256,T=1024,HID=150 — R15: R12 math (fp32-acc HMMA, 864us)
// + warp-local pointwise via GEMM row permutation.
// Warp w's 5 M-tiles hold warp-rows q=0..79 mapped to (gate=q/20,
// unit=20*wid+q%20): all 4 gates of the warp's 20 units stay inside the
// warp. Extraction stages D in a warp-PRIVATE smem patch (__syncwarp only),
// then all 32 lanes update the warp's 40 (unit,batch) items. Barrier #1 is
// gone; hk/hbuf are ping-pong buffered so the single end-of-step
// __syncthreads suffices. wih/bias live in smem. tanh.approx activations.

namespace {

constexpr int HID = 150, TT = 1024, NCTA = 128, NTHR = 256;
constexpr int KT = 10;            // K-tiles of 16 (K padded to 160)
constexpr int HKP = 168;          // h row pitch in halves (bank-clean)

// dynamic smem offsets (bytes)
constexpr int OFF_HK   = 0;                 // fp16 h [2buf][8][168] = 5376
constexpr int OFF_HBUF = 5376;              // fp32 h [2buf][2][152] = 2432
constexpr int OFF_WG   = 7808;              // float2 [8 warps][80] = 5120
constexpr int OFF_WLIN = 12928;             // fp32 [160] = 640
constexpr int OFF_BIAS = 13568;             // fp32 [600] = 2400
constexpr int OFF_WIH  = 15968;             // fp32 [600] = 2400
constexpr int OFF_W5   = 18368;             // uint4 A-frags tile i=4: 40960
constexpr int OFF_XIN  = 59328;             // fp32 [2][1024] = 8192
constexpr int SMEM_BYTES = 67520;

__device__ __forceinline__ float tanhapx(float x) {
    float y;
    asm("tanh.approx.f32 %0, %1;" : "=f"(y) : "f"(x));
    return y;
}
__device__ __forceinline__ float sigapx(float x) {
    return fmaf(tanhapx(0.5f * x), 0.5f, 0.5f);
}

__device__ __forceinline__ void mma16816(float& d0, float& d1, float& d2,
                                         float& d3, uint32_t a0, uint32_t a1,
                                         uint32_t a2, uint32_t a3,
                                         uint32_t b0, uint32_t b1) {
    asm volatile(
        "mma.sync.aligned.m16n8k16.row.col.f32.f16.f16.f32 "
        "{%0,%1,%2,%3}, {%4,%5,%6,%7}, {%8,%9}, {%0,%1,%2,%3};"
        : "+f"(d0), "+f"(d1), "+f"(d2), "+f"(d3)
        : "r"(a0), "r"(a1), "r"(a2), "r"(a3), "r"(b0), "r"(b1));
}

// Permuted W_hh element: warp-row q -> (gate=q/20, unit=20*wid+q%20)
__device__ __forceinline__ float wrow(const float* W, int gate, int u, int c) {
    return (u < HID && c < HID) ? W[(gate * HID + u) * HID + c] : 0.f;
}
__device__ __forceinline__ uint32_t h2u(__half2 v) {
    return *reinterpret_cast<uint32_t*>(&v);
}

} // namespace

__global__ void __launch_bounds__(NTHR, 1)
lstm_hmma_kernel(const float* __restrict__ input,   // [256][1024]
                 const float* __restrict__ W_ih,    // [600][1]
                 const float* __restrict__ W_hh,    // [600][150]
                 const float* __restrict__ b_ih,    // [600]
                 const float* __restrict__ b_hh,    // [600]
                 const float* __restrict__ W_lin,   // [1][150]
                 const float* __restrict__ b_lin,   // [1]
                 float* __restrict__ out)           // [256][1024]
{
    extern __shared__ char smem[];
    __half* hk     = reinterpret_cast<__half*>(smem + OFF_HK);
    float*  hbuf   = reinterpret_cast<float*>(smem + OFF_HBUF);
    float2* wg     = reinterpret_cast<float2*>(smem + OFF_WG);
    float*  wlin_s = reinterpret_cast<float*>(smem + OFF_WLIN);
    float*  bias_s = reinterpret_cast<float*>(smem + OFF_BIAS);
    float*  wih_s  = reinterpret_cast<float*>(smem + OFF_WIH);
    uint4*  w5     = reinterpret_cast<uint4*>(smem + OFF_W5);
    float*  xin    = reinterpret_cast<float*>(smem + OFF_XIN);

    const int tid  = threadIdx.x;
    const int wid  = tid >> 5;
    const int lane = tid & 31;
    const int g    = lane >> 2;      // fragment row-group 0..7
    const int tig  = lane & 3;       // thread-in-group
    const int b0   = blockIdx.x * 2;

    // ---- one-time init ----
    for (int i = tid; i < 2 * 8 * HKP; i += NTHR) hk[i] = __half(0);
    for (int i = tid; i < 2 * 2 * 152; i += NTHR) hbuf[i] = 0.f;
    for (int i = tid; i < HID; i += NTHR) wlin_s[i] = W_lin[i];
    for (int i = tid; i < 600; i += NTHR) {
        bias_s[i] = b_ih[i] + b_hh[i];
        wih_s[i]  = W_ih[i];
    }
    for (int i = tid; i < 2 * TT; i += NTHR)
        xin[i] = input[(b0 + (i >> 10)) * TT + (i & (TT - 1))];

    // A fragments, PERMUTED rows: warp-row q of warp wid = (gate, unit).
    // GEMM rows of tile i: q0 = 16i+g, q1 = 16i+8+g.
    uint32_t af[4][KT][4];
#pragma unroll
    for (int i = 0; i < 5; ++i) {
        const int q0 = 16 * i + g, q1 = q0 + 8;
        const int ga0 = q0 / 20, u0 = 20 * wid + q0 % 20;
        const int ga1 = q1 / 20, u1 = 20 * wid + q1 % 20;
#pragma unroll
        for (int kt = 0; kt < KT; ++kt) {
            const int kb = 16 * kt + 2 * tig;
            uint32_t f0 = h2u(__floats2half2_rn(wrow(W_hh, ga0, u0, kb),
                                                wrow(W_hh, ga0, u0, kb + 1)));
            uint32_t f1 = h2u(__floats2half2_rn(wrow(W_hh, ga1, u1, kb),
                                                wrow(W_hh, ga1, u1, kb + 1)));
            uint32_t f2 = h2u(__floats2half2_rn(wrow(W_hh, ga0, u0, kb + 8),
                                                wrow(W_hh, ga0, u0, kb + 9)));
            uint32_t f3 = h2u(__floats2half2_rn(wrow(W_hh, ga1, u1, kb + 8),
                                                wrow(W_hh, ga1, u1, kb + 9)));
            if (i < 4) {
                af[i][kt][0] = f0; af[i][kt][1] = f1;
                af[i][kt][2] = f2; af[i][kt][3] = f3;
            } else {
                w5[(wid * KT + kt) * 32 + lane] = make_uint4(f0, f1, f2, f3);
            }
        }
    }

    // Per-lane pointwise items (fixed all steps):
    //  item0 (all lanes): m=lane  -> b=m/20, ul=m%20
    //  item1 (lane<8):    m=32+l  -> b=1,    ul=12+l
    const int ul0 = lane % 20, bI0 = lane / 20;
    const int ul1 = 12 + lane; // only lanes < 8, batch 1
    const int uA  = 20 * wid + ul0;
    const int uB  = 20 * wid + ul1;
    float cA = 0.f, cB = 0.f;
    const float blin = b_lin[0];
    float2* wgw = wg + wid * 80;
    const float* wgf = reinterpret_cast<const float*>(wgw);

    __syncthreads();

    for (int t = 0; t < TT; ++t) {
        const int cur = t & 1, nxt = cur ^ 1;
        const __half* hkc = hk + cur * 8 * HKP;

        // ---- overlapped output: out[t-1] from hbuf[cur] (warps 4,5) ----
        if (t && (wid == 4 || wid == 5)) {
            const int bb = wid - 4;
            const float* hb = hbuf + cur * 2 * 152 + bb * 152;
            float s = 0.f;
#pragma unroll
            for (int m = 0; m < 5; ++m) {
                const int jj = lane + 32 * m;
                if (jj < HID) s = fmaf(hb[jj], wlin_s[jj], s);
            }
#pragma unroll
            for (int off = 16; off; off >>= 1)
                s += __shfl_down_sync(0xffffffffu, s, off);
            if (lane == 0) out[(b0 + bb) * TT + (t - 1)] = s + blin;
        }

        // ---- B fragments from h_{t-1} (conflict-free LDS.32, as R12) ----
        uint32_t bf[KT][2];
#pragma unroll
        for (int kt = 0; kt < KT; ++kt) {
            const int base = g * HKP + 16 * kt + 2 * tig;
            bf[kt][0] = *reinterpret_cast<const uint32_t*>(hkc + base);
            bf[kt][1] = *reinterpret_cast<const uint32_t*>(hkc + base + 8);
        }

        // ---- 5 M-tiles x 10 K-tiles of HMMA (fp32 acc, R12 layout) ----
#pragma unroll
        for (int i = 0; i < 5; ++i) {
            float d0 = 0.f, d1 = 0.f, d2 = 0.f, d3 = 0.f;
            if (i < 4) {
#pragma unroll
                for (int kt = 0; kt < KT; ++kt)
                    mma16816(d0, d1, d2, d3, af[i][kt][0], af[i][kt][1],
                             af[i][kt][2], af[i][kt][3], bf[kt][0], bf[kt][1]);
            } else {
#pragma unroll
                for (int kt = 0; kt < KT; ++kt) {
                    const uint4 q = w5[(wid * KT + kt) * 32 + lane];
                    mma16816(d0, d1, d2, d3, q.x, q.y, q.z, q.w,
                             bf[kt][0], bf[kt][1]);
                }
            }
            if (tig == 0) {           // warp-private staging: no barrier
                wgw[16 * i + g]     = make_float2(d0, d1);
                wgw[16 * i + 8 + g] = make_float2(d2, d3);
            }
        }
        __syncwarp();

        // ---- warp-local pointwise: 40 items over 32 lanes ----
        float* hbn = hbuf + nxt * 2 * 152;
        __half* hkn = hk + nxt * 8 * HKP;
        {   // item 0 (all lanes)
            if (uA < HID) {
                const float xb = xin[bI0 * TT + t];
                const float gi = wgf[(ul0) * 2 + bI0] +
                                 fmaf(xb, wih_s[uA], bias_s[uA]);
                const float gf = wgf[(20 + ul0) * 2 + bI0] +
                                 fmaf(xb, wih_s[HID + uA], bias_s[HID + uA]);
                const float gg = wgf[(40 + ul0) * 2 + bI0] +
                                 fmaf(xb, wih_s[2 * HID + uA], bias_s[2 * HID + uA]);
                const float go = wgf[(60 + ul0) * 2 + bI0] +
                                 fmaf(xb, wih_s[3 * HID + uA], bias_s[3 * HID + uA]);
                cA = fmaf(sigapx(gf), cA, sigapx(gi) * tanhapx(gg));
                const float h = sigapx(go) * tanhapx(cA);
                hbn[bI0 * 152 + uA] = h;
                hkn[bI0 * HKP + uA] = __float2half(h);
            }
        }
        if (lane < 8 && uB < HID) {   // item 1 (batch 1)
            const float xb = xin[TT + t];
            const float gi = wgf[(ul1) * 2 + 1] +
                             fmaf(xb, wih_s[uB], bias_s[uB]);
            const float gf = wgf[(20 + ul1) * 2 + 1] +
                             fmaf(xb, wih_s[HID + uB], bias_s[HID + uB]);
            const float gg = wgf[(40 + ul1) * 2 + 1] +
                             fmaf(xb, wih_s[2 * HID + uB], bias_s[2 * HID + uB]);
            const float go = wgf[(60 + ul1) * 2 + 1] +
                             fmaf(xb, wih_s[3 * HID + uB], bias_s[3 * HID + uB]);
            cB = fmaf(sigapx(gf), cB, sigapx(gi) * tanhapx(gg));
            const float h = sigapx(go) * tanhapx(cB);
            hbn[152 + uB] = h;
            hkn[HKP + uB] = __float2half(h);
        }
        __syncthreads();              // h_t visible to all warps for t+1
    }

    // ---- epilogue: out[TT-1] from hbuf[buf 0] (TT even) ----
    if (wid == 4 || wid == 5) {
        const int bb = wid - 4;
        const float* hb = hbuf + (TT & 1) * 2 * 152 + bb * 152;
        float s = 0.f;
#pragma unroll
        for (int m = 0; m < 5; ++m) {
            const int jj = lane + 32 * m;
            if (jj < HID) s = fmaf(hb[jj], wlin_s[jj], s);
        }
#pragma unroll
        for (int off = 16; off; off >>= 1)
            s += __shfl_down_sync(0xffffffffu, s, off);
        if (lane == 0) out[(b0 + bb) * TT + (TT - 1)] = s + blin;
    }
}

extern "C" void kernel_launch(void* const* d_in, const int* in_sizes, int n_in,
                              void* d_out, int out_size) {
    const float* input = (const float*)d_in[0];
    const float* W_ih  = (const float*)d_in[1];
    const float* W_hh  = (const float*)d_in[2];
    const float* b_ih  = (const float*)d_in[3];
    const float* b_hh  = (const float*)d_in[4];
    const float* W_lin = (const float*)d_in[5];
    const float* b_lin = (const float*)d_in[6];
    float* out = (float*)d_out;

    cudaFuncSetAttribute(lstm_hmma_kernel,
                         cudaFuncAttributeMaxDynamicSharedMemorySize, SMEM_BYTES);
    lstm_hmma_kernel<<<NCTA, NTHR, SMEM_BYTES>>>(input, W_ih, W_hh, b_ih, b_hh,
                                                 W_lin, b_lin, out);
}